// round 1
// baseline (speedup 1.0000x reference)
#include <cuda_runtime.h>
#include <math.h>

#define NN 50000
#define DD 128
#define EE 500000
#define WPAD 132   // padded row stride (floats) for transposed weight tiles in smem

// ---------------- device scratch (no allocs allowed) ----------------
static __device__ float g_A1a[NN*DD];   // lrelu(x_a@Wp.T+bp) @ W1p.T
static __device__ float g_C1a[NN*DD];   // lrelu(x_a@Wc.T+bc) @ W1c.T
static __device__ float g_A1b[NN*DD];
static __device__ float g_C1b[NN*DD];
static __device__ float g_msg_a[NN*DD];
static __device__ float g_msg_b[NN*DD];

// ---------------- zero the message accumulators ----------------
__global__ void zero_kernel() {
    int i = blockIdx.x * blockDim.x + threadIdx.x;
    float4 z = make_float4(0.f, 0.f, 0.f, 0.f);
    if (i < NN * DD / 4) {
        reinterpret_cast<float4*>(g_msg_a)[i] = z;
        reinterpret_cast<float4*>(g_msg_b)[i] = z;
    }
}

// ---------------- node precompute: Out = lrelu(X@W.T + b) @ U.T ----------------
// chain: 0 -> (x_a, Wp, off 0)   -> g_A1a
//        1 -> (x_a, Wc, off 128) -> g_C1a
//        2 -> (x_b, Wp, off 0)   -> g_A1b
//        3 -> (x_b, Wc, off 128) -> g_C1b
// U[i][j] = W1[i*384 + off + j]
__global__ __launch_bounds__(256) void node_pre_kernel(
    const float* __restrict__ x_a, const float* __restrict__ x_b,
    const float* __restrict__ Wp, const float* __restrict__ bp,
    const float* __restrict__ Wc, const float* __restrict__ bc,
    const float* __restrict__ W1)
{
    extern __shared__ float sm[];
    float* Wt = sm;                 // [128][WPAD] transposed first weight
    float* Ut = sm + 128 * WPAD;    // [128][WPAD] transposed second weight
    float* xs = Ut + 128 * WPAD;    // [32][128] node rows
    float* ts = xs + 32 * 128;      // [32][128] intermediate rows

    int chain = blockIdx.y;
    const float* X  = (chain & 2) ? x_b : x_a;
    const float* W  = (chain & 1) ? Wc : Wp;
    const float* bv = (chain & 1) ? bc : bp;
    int off = (chain & 1) ? 128 : 0;
    float* Out = (chain == 0) ? g_A1a : (chain == 1) ? g_C1a
               : (chain == 2) ? g_A1b : g_C1b;

    int tid = threadIdx.x;
    // load both weights transposed (coalesced read, small bank-conflicted write)
    for (int idx = tid; idx < 128 * 128; idx += 256) {
        int i = idx >> 7, j = idx & 127;
        Wt[j * WPAD + i] = W[i * 128 + j];
        Ut[j * WPAD + i] = W1[i * 384 + off + j];
    }

    int lane = tid & 31, warp = tid >> 5;
    int nbase = blockIdx.x * 32;
    // cooperative load of 32 node rows
    for (int idx = tid * 4; idx < 32 * 128; idx += 256 * 4) {
        int row = idx >> 7, col = idx & 127;
        int n = nbase + row;
        float4 v = make_float4(0.f, 0.f, 0.f, 0.f);
        if (n < NN) v = *reinterpret_cast<const float4*>(X + (size_t)n * 128 + col);
        *reinterpret_cast<float4*>(xs + row * 128 + col) = v;
    }
    __syncthreads();

    float4 b4 = make_float4(bv[4*lane], bv[4*lane+1], bv[4*lane+2], bv[4*lane+3]);

    // phase 1: tmp = lrelu(X@W.T + b), warp owns 4 nodes, lane owns 4 cols
    float4 acc[4];
    #pragma unroll
    for (int k = 0; k < 4; k++) acc[k] = make_float4(0.f, 0.f, 0.f, 0.f);
    const float* xrow = xs + warp * 4 * 128;
    #pragma unroll 4
    for (int j = 0; j < 128; j++) {
        float4 wv = *reinterpret_cast<const float4*>(Wt + j * WPAD + 4 * lane);
        #pragma unroll
        for (int k = 0; k < 4; k++) {
            float a = xrow[k * 128 + j];
            acc[k].x = fmaf(a, wv.x, acc[k].x);
            acc[k].y = fmaf(a, wv.y, acc[k].y);
            acc[k].z = fmaf(a, wv.z, acc[k].z);
            acc[k].w = fmaf(a, wv.w, acc[k].w);
        }
    }
    float* trow = ts + warp * 4 * 128;
    #pragma unroll
    for (int k = 0; k < 4; k++) {
        float4 t;
        float vx = acc[k].x + b4.x; t.x = vx > 0.f ? vx : 0.01f * vx;
        float vy = acc[k].y + b4.y; t.y = vy > 0.f ? vy : 0.01f * vy;
        float vz = acc[k].z + b4.z; t.z = vz > 0.f ? vz : 0.01f * vz;
        float vw = acc[k].w + b4.w; t.w = vw > 0.f ? vw : 0.01f * vw;
        *reinterpret_cast<float4*>(trow + k * 128 + 4 * lane) = t;
    }
    __syncwarp();

    // phase 2: Out = tmp @ U.T
    #pragma unroll
    for (int k = 0; k < 4; k++) acc[k] = make_float4(0.f, 0.f, 0.f, 0.f);
    #pragma unroll 4
    for (int j = 0; j < 128; j++) {
        float4 uv = *reinterpret_cast<const float4*>(Ut + j * WPAD + 4 * lane);
        #pragma unroll
        for (int k = 0; k < 4; k++) {
            float a = trow[k * 128 + j];
            acc[k].x = fmaf(a, uv.x, acc[k].x);
            acc[k].y = fmaf(a, uv.y, acc[k].y);
            acc[k].z = fmaf(a, uv.z, acc[k].z);
            acc[k].w = fmaf(a, uv.w, acc[k].w);
        }
    }
    #pragma unroll
    for (int k = 0; k < 4; k++) {
        int n = nbase + warp * 4 + k;
        if (n < NN)
            *reinterpret_cast<float4*>(Out + (size_t)n * 128 + 4 * lane) = acc[k];
    }
}

// ---------------- edge kernel: per-edge weight + scatter ----------------
// h = relu(A1[s] + C1[t] + b1 + |x_src[s]-x_dst[t]| @ W1d.T)
// w = sigmoid(h . w2 + b2);  msg[t] += w * x_src[s]
__global__ __launch_bounds__(256) void edge_kernel(
    const float* __restrict__ x_a, const float* __restrict__ x_b,
    const int* __restrict__ ei,
    const float* __restrict__ W1, const float* __restrict__ b1,
    const float* __restrict__ W2, const float* __restrict__ b2,
    int side)
{
    extern __shared__ float sm[];
    float* Ut = sm;              // [128][WPAD] transposed W1d
    float* ds = sm + 128 * WPAD; // [8 warps][4 edges][128] |par-cld|

    const float* src = side ? x_b : x_a;
    const float* dst = side ? x_a : x_b;
    const float* A1  = side ? g_A1b : g_A1a;
    const float* C1  = side ? g_C1a : g_C1b;
    float* msg       = side ? g_msg_a : g_msg_b;

    int tid = threadIdx.x, lane = tid & 31, warp = tid >> 5;
    for (int idx = tid; idx < 128 * 128; idx += 256) {
        int i = idx >> 7, j = idx & 127;
        Ut[j * WPAD + i] = W1[i * 384 + 256 + j];   // W1d slice
    }
    __syncthreads();

    float4 b1v = *reinterpret_cast<const float4*>(b1 + 4 * lane);
    float4 w2v = *reinterpret_cast<const float4*>(W2 + 4 * lane);
    float  b2s = b2[0];

    float* dsw = ds + warp * 4 * 128;
    const int ntiles = EE / 32;   // 500000 / 32 = 15625 exact
    for (int tile = blockIdx.x; tile < ntiles; tile += gridDim.x) {
        int ebase = tile * 32 + warp * 4;
        float4 par[4], pre[4], acc[4];
        int tIdx[4];
        #pragma unroll
        for (int k = 0; k < 4; k++) {
            int e = ebase + k;
            int s = ei[e];
            int t = ei[EE + e];
            tIdx[k] = t;
            float4 p = *reinterpret_cast<const float4*>(src + (size_t)s * 128 + 4 * lane);
            float4 c = *reinterpret_cast<const float4*>(dst + (size_t)t * 128 + 4 * lane);
            par[k] = p;
            float4 d = make_float4(fabsf(p.x - c.x), fabsf(p.y - c.y),
                                   fabsf(p.z - c.z), fabsf(p.w - c.w));
            *reinterpret_cast<float4*>(dsw + k * 128 + 4 * lane) = d;
            float4 a1 = *reinterpret_cast<const float4*>(A1 + (size_t)s * 128 + 4 * lane);
            float4 c1 = *reinterpret_cast<const float4*>(C1 + (size_t)t * 128 + 4 * lane);
            pre[k] = make_float4(a1.x + c1.x + b1v.x, a1.y + c1.y + b1v.y,
                                 a1.z + c1.z + b1v.z, a1.w + c1.w + b1v.w);
            acc[k] = make_float4(0.f, 0.f, 0.f, 0.f);
        }
        __syncwarp();

        #pragma unroll 4
        for (int j = 0; j < 128; j++) {
            float4 wv = *reinterpret_cast<const float4*>(Ut + j * WPAD + 4 * lane);
            #pragma unroll
            for (int k = 0; k < 4; k++) {
                float a = dsw[k * 128 + j];
                acc[k].x = fmaf(a, wv.x, acc[k].x);
                acc[k].y = fmaf(a, wv.y, acc[k].y);
                acc[k].z = fmaf(a, wv.z, acc[k].z);
                acc[k].w = fmaf(a, wv.w, acc[k].w);
            }
        }

        #pragma unroll
        for (int k = 0; k < 4; k++) {
            float hx = fmaxf(pre[k].x + acc[k].x, 0.f);
            float hy = fmaxf(pre[k].y + acc[k].y, 0.f);
            float hz = fmaxf(pre[k].z + acc[k].z, 0.f);
            float hw = fmaxf(pre[k].w + acc[k].w, 0.f);
            float z = hx * w2v.x + hy * w2v.y + hz * w2v.z + hw * w2v.w;
            #pragma unroll
            for (int offs = 16; offs; offs >>= 1)
                z += __shfl_xor_sync(0xffffffffu, z, offs);
            float wgt = 1.f / (1.f + expf(-(z + b2s)));
            float* mrow = msg + (size_t)tIdx[k] * 128 + 4 * lane;
            atomicAdd(mrow + 0, wgt * par[k].x);
            atomicAdd(mrow + 1, wgt * par[k].y);
            atomicAdd(mrow + 2, wgt * par[k].z);
            atomicAdd(mrow + 3, wgt * par[k].w);
        }
        __syncwarp();   // protect dsw before next tile overwrites it
    }
}

// ---------------- output: out = msg@Wrel.T + x@Wroot.T + (brel+broot) ----------------
__global__ __launch_bounds__(256) void final_kernel(
    const float* __restrict__ x,
    const float* __restrict__ Wrel, const float* __restrict__ brel,
    const float* __restrict__ Wroot, const float* __restrict__ broot,
    float* __restrict__ out, int side)
{
    extern __shared__ float sm[];
    float* Rt = sm;
    float* Ot = sm + 128 * WPAD;
    float* ms = Ot + 128 * WPAD;
    float* xs = ms + 32 * 128;
    const float* msg = side ? g_msg_b : g_msg_a;

    int tid = threadIdx.x;
    for (int idx = tid; idx < 128 * 128; idx += 256) {
        int i = idx >> 7, j = idx & 127;
        Rt[j * WPAD + i] = Wrel[i * 128 + j];
        Ot[j * WPAD + i] = Wroot[i * 128 + j];
    }
    int nbase = blockIdx.x * 32;
    for (int idx = tid * 4; idx < 32 * 128; idx += 256 * 4) {
        int row = idx >> 7, col = idx & 127;
        int n = nbase + row;
        float4 mv = make_float4(0.f, 0.f, 0.f, 0.f), xv = mv;
        if (n < NN) {
            mv = *reinterpret_cast<const float4*>(msg + (size_t)n * 128 + col);
            xv = *reinterpret_cast<const float4*>(x   + (size_t)n * 128 + col);
        }
        *reinterpret_cast<float4*>(ms + row * 128 + col) = mv;
        *reinterpret_cast<float4*>(xs + row * 128 + col) = xv;
    }
    __syncthreads();

    int lane = tid & 31, warp = tid >> 5;
    float4 bs = make_float4(brel[4*lane+0] + broot[4*lane+0],
                            brel[4*lane+1] + broot[4*lane+1],
                            brel[4*lane+2] + broot[4*lane+2],
                            brel[4*lane+3] + broot[4*lane+3]);
    float4 acc[4];
    #pragma unroll
    for (int k = 0; k < 4; k++) acc[k] = bs;
    const float* mrow = ms + warp * 4 * 128;
    const float* xrow = xs + warp * 4 * 128;
    #pragma unroll 2
    for (int j = 0; j < 128; j++) {
        float4 rv = *reinterpret_cast<const float4*>(Rt + j * WPAD + 4 * lane);
        float4 ov = *reinterpret_cast<const float4*>(Ot + j * WPAD + 4 * lane);
        #pragma unroll
        for (int k = 0; k < 4; k++) {
            float m  = mrow[k * 128 + j];
            float xv = xrow[k * 128 + j];
            acc[k].x = fmaf(m, rv.x, fmaf(xv, ov.x, acc[k].x));
            acc[k].y = fmaf(m, rv.y, fmaf(xv, ov.y, acc[k].y));
            acc[k].z = fmaf(m, rv.z, fmaf(xv, ov.z, acc[k].z));
            acc[k].w = fmaf(m, rv.w, fmaf(xv, ov.w, acc[k].w));
        }
    }
    #pragma unroll
    for (int k = 0; k < 4; k++) {
        int n = nbase + warp * 4 + k;
        if (n < NN)
            *reinterpret_cast<float4*>(out + (size_t)n * 128 + 4 * lane) = acc[k];
    }
}

// ---------------- host ----------------
extern "C" void kernel_launch(void* const* d_in, const int* in_sizes, int n_in,
                              void* d_out, int out_size)
{
    const float* x_a = (const float*)d_in[0];
    const float* x_b = (const float*)d_in[1];
    const float* Wp  = (const float*)d_in[2];
    const float* bp  = (const float*)d_in[3];
    const float* Wc  = (const float*)d_in[4];
    const float* bc  = (const float*)d_in[5];
    const float* W1  = (const float*)d_in[6];
    const float* b1  = (const float*)d_in[7];
    const float* W2  = (const float*)d_in[8];
    const float* b2  = (const float*)d_in[9];
    const float* Wrel_ab  = (const float*)d_in[10];
    const float* brel_ab  = (const float*)d_in[11];
    const float* Wroot_ab = (const float*)d_in[12];
    const float* broot_ab = (const float*)d_in[13];
    const float* Wrel_ba  = (const float*)d_in[14];
    const float* brel_ba  = (const float*)d_in[15];
    const float* Wroot_ba = (const float*)d_in[16];
    const float* broot_ba = (const float*)d_in[17];
    const int* ei_ab = (const int*)d_in[18];
    const int* ei_ba = (const int*)d_in[19];
    float* out = (float*)d_out;

    const int NODE_SMEM = (128 * WPAD * 2 + 32 * 128 * 2) * 4;  // 167936 B
    const int EDGE_SMEM = (128 * WPAD + 32 * 128) * 4;          // 83968 B
    cudaFuncSetAttribute(node_pre_kernel, cudaFuncAttributeMaxDynamicSharedMemorySize, NODE_SMEM);
    cudaFuncSetAttribute(edge_kernel,     cudaFuncAttributeMaxDynamicSharedMemorySize, EDGE_SMEM);
    cudaFuncSetAttribute(final_kernel,    cudaFuncAttributeMaxDynamicSharedMemorySize, NODE_SMEM);

    zero_kernel<<<(NN * DD / 4 + 255) / 256, 256>>>();
    node_pre_kernel<<<dim3((NN + 31) / 32, 4), 256, NODE_SMEM>>>(x_a, x_b, Wp, bp, Wc, bc, W1);
    edge_kernel<<<1184, 256, EDGE_SMEM>>>(x_a, x_b, ei_ab, W1, b1, W2, b2, 0);
    edge_kernel<<<1184, 256, EDGE_SMEM>>>(x_a, x_b, ei_ba, W1, b1, W2, b2, 1);
    final_kernel<<<(NN + 31) / 32, 256, NODE_SMEM>>>(x_a, Wrel_ba, brel_ba, Wroot_ba, broot_ba, out, 0);
    final_kernel<<<(NN + 31) / 32, 256, NODE_SMEM>>>(x_b, Wrel_ab, brel_ab, Wroot_ab, broot_ab, out + (size_t)NN * DD, 1);
}